// round 3
// baseline (speedup 1.0000x reference)
#include <cuda_runtime.h>
#include <math.h>

// Problem constants
#define NTOK  4096      // B*T
#define TSEQ  2048
#define EMBED 1024
#define NH    16
#define HDIM  64

// Scratch (device globals: allocation-free per harness rules)
__device__ float g_Q[(size_t)NTOK * EMBED];
__device__ float g_K[(size_t)NTOK * EMBED];
__device__ float g_V[(size_t)NTOK * EMBED];
__device__ float g_A[(size_t)NTOK * EMBED];

// ---------------------------------------------------------------------------
// SGEMM: D = A[4096,1024] @ W[1024,1024] + bias, with up to 3 (W,bias,D) sets
// selected by blockIdx.z (fused QKV projection; z=1 grid for O projection).
// 128x128 tile, BK=8, 256 threads, 8x8 per-thread microkernel.
// ---------------------------------------------------------------------------
__global__ __launch_bounds__(256, 2)
void sgemm_bias3(const float* __restrict__ A,
                 const float* __restrict__ W0, const float* __restrict__ W1,
                 const float* __restrict__ W2,
                 const float* __restrict__ c0, const float* __restrict__ c1,
                 const float* __restrict__ c2,
                 float* __restrict__ D0, float* __restrict__ D1,
                 float* __restrict__ D2)
{
    constexpr int K  = EMBED;
    constexpr int M  = EMBED;
    constexpr int BK = 8;

    const float* W    = W0;
    const float* bias = c0;
    float*       D    = D0;
    if (blockIdx.z == 1)      { W = W1; bias = c1; D = D1; }
    else if (blockIdx.z == 2) { W = W2; bias = c2; D = D2; }

    __shared__ float As[BK][128];   // A tile, stored transposed [k][m]
    __shared__ float Bs[BK][128];   // W tile [k][n]

    const int tid = threadIdx.x;
    const int tx  = tid & 15;       // n-group
    const int ty  = tid >> 4;       // m-group
    const int bm  = blockIdx.y * 128;
    const int bn  = blockIdx.x * 128;

    // Load assignments
    const int a_row = tid >> 1;          // 0..127
    const int a_col = (tid & 1) * 4;     // 0 or 4
    const int b_row = tid >> 5;          // 0..7
    const int b_col = (tid & 31) * 4;    // 0..124

    const float* Ap = A + (size_t)(bm + a_row) * K + a_col;
    const float* Wp = W + (size_t)b_row * M + bn + b_col;

    float acc[8][8];
#pragma unroll
    for (int i = 0; i < 8; i++)
#pragma unroll
        for (int j = 0; j < 8; j++) acc[i][j] = 0.0f;

    for (int k0 = 0; k0 < K; k0 += BK) {
        float4 av = *(const float4*)Ap;
        float4 wv = *(const float4*)Wp;
        __syncthreads();
        As[a_col + 0][a_row] = av.x;
        As[a_col + 1][a_row] = av.y;
        As[a_col + 2][a_row] = av.z;
        As[a_col + 3][a_row] = av.w;
        *(float4*)&Bs[b_row][b_col] = wv;
        __syncthreads();
        Ap += BK;
        Wp += (size_t)BK * M;

#pragma unroll
        for (int k = 0; k < BK; k++) {
            float a[8], b[8];
            *(float4*)&a[0] = *(const float4*)&As[k][ty * 4];
            *(float4*)&a[4] = *(const float4*)&As[k][64 + ty * 4];
            *(float4*)&b[0] = *(const float4*)&Bs[k][tx * 4];
            *(float4*)&b[4] = *(const float4*)&Bs[k][64 + tx * 4];
#pragma unroll
            for (int i = 0; i < 8; i++)
#pragma unroll
                for (int j = 0; j < 8; j++)
                    acc[i][j] = fmaf(a[i], b[j], acc[i][j]);
        }
    }

    // Epilogue with bias
#pragma unroll
    for (int ii = 0; ii < 2; ii++) {
#pragma unroll
        for (int i = 0; i < 4; i++) {
            const int row = bm + ii * 64 + ty * 4 + i;
#pragma unroll
            for (int jj = 0; jj < 2; jj++) {
                const int col = bn + jj * 64 + tx * 4;
                float4 o;
                o.x = acc[ii * 4 + i][jj * 4 + 0] + bias[col + 0];
                o.y = acc[ii * 4 + i][jj * 4 + 1] + bias[col + 1];
                o.z = acc[ii * 4 + i][jj * 4 + 2] + bias[col + 2];
                o.w = acc[ii * 4 + i][jj * 4 + 3] + bias[col + 3];
                *(float4*)&D[(size_t)row * M + col] = o;
            }
        }
    }
}

// ---------------------------------------------------------------------------
// Flash attention (causal), fp32.
// Q/K/V layout: [B*T, 1024]; head h occupies columns h*64..h*64+63.
// One CTA per (q-tile of 64 rows, head, batch). 256 threads = 16x16 grid,
// each thread computes a 4x4 tile of S and a 4x4 tile of O.
// SMEM: Qs[64][64] + KsP[64][64] (K^T swizzled, then reused for P) + Vs[64][64]
//       = 48 KB exactly.
// ---------------------------------------------------------------------------
__device__ __forceinline__ int ksw(int d, int kslot) {
    // XOR swizzle: conflict-free float4 reads per row, ~2-way store conflicts
    return kslot ^ ((d >> 2) & 15) ^ ((d & 3) << 2);
}

__global__ __launch_bounds__(256, 2)
void flash_attn(const float* __restrict__ Q, const float* __restrict__ K,
                const float* __restrict__ V, float* __restrict__ O)
{
    __shared__ float Qs[64][HDIM];
    __shared__ float KsP[64][64];   // phase 1: K^T (swizzled) ; phase 2: P
    __shared__ float Vs[64][HDIM];

    const int tid = threadIdx.x;
    const int tx  = tid & 15;       // k-col / d-col group
    const int ty  = tid >> 4;       // q-row group
    const int qt  = blockIdx.x;     // q tile (0..31)
    const int h   = blockIdx.y;
    const int b   = blockIdx.z;

    const size_t base = (size_t)b * TSEQ * EMBED + (size_t)h * HDIM;
    const int q0 = qt * 64;

    // Load Q tile [64 x 64]
    {
        const float* Qb = Q + base + (size_t)q0 * EMBED;
#pragma unroll
        for (int it = 0; it < 4; it++) {
            const int i = tid + it * 256;
            const int r = i >> 4;
            const int c = (i & 15) << 2;
            *(float4*)&Qs[r][c] = *(const float4*)(Qb + (size_t)r * EMBED + c);
        }
    }

    float acc[4][4];
    float m_i[4], l_i[4];
#pragma unroll
    for (int i = 0; i < 4; i++) {
        m_i[i] = -1e30f;
        l_i[i] = 0.0f;
#pragma unroll
        for (int j = 0; j < 4; j++) acc[i][j] = 0.0f;
    }

    const float scale = 0.125f;  // HDIM^-0.5

    for (int j = 0; j <= qt; j++) {
        const float* Kb = K + base + (size_t)(j * 64) * EMBED;
        const float* Vb = V + base + (size_t)(j * 64) * EMBED;

        __syncthreads();  // previous iteration's readers of KsP/Vs done; Qs ready (iter 0)

        // Load K (transposed+swizzled) and V tiles
#pragma unroll
        for (int it = 0; it < 4; it++) {
            const int i = tid + it * 256;
            const int r = i >> 4;          // k index
            const int c = (i & 15) << 2;   // d index base
            float4 kv = *(const float4*)(Kb + (size_t)r * EMBED + c);
            KsP[c + 0][(ksw(c + 0, r >> 2) << 2) + (r & 3)] = kv.x;
            KsP[c + 1][(ksw(c + 1, r >> 2) << 2) + (r & 3)] = kv.y;
            KsP[c + 2][(ksw(c + 2, r >> 2) << 2) + (r & 3)] = kv.z;
            KsP[c + 3][(ksw(c + 3, r >> 2) << 2) + (r & 3)] = kv.w;
            *(float4*)&Vs[r][c] = *(const float4*)(Vb + (size_t)r * EMBED + c);
        }
        __syncthreads();

        // S = Q K^T  (4x4 per thread)
        float s[4][4];
#pragma unroll
        for (int i = 0; i < 4; i++)
#pragma unroll
            for (int jj = 0; jj < 4; jj++) s[i][jj] = 0.0f;

#pragma unroll
        for (int d = 0; d < HDIM; d += 4) {
            float qv[4][4], kk[4][4];
#pragma unroll
            for (int i = 0; i < 4; i++)
                *(float4*)qv[i] = *(const float4*)&Qs[ty * 4 + i][d];
#pragma unroll
            for (int dd = 0; dd < 4; dd++)
                *(float4*)kk[dd] = *(const float4*)&KsP[d + dd][ksw(d + dd, tx) << 2];
#pragma unroll
            for (int i = 0; i < 4; i++)
#pragma unroll
                for (int jj = 0; jj < 4; jj++) {
                    s[i][jj] = fmaf(qv[i][0], kk[0][jj], s[i][jj]);
                    s[i][jj] = fmaf(qv[i][1], kk[1][jj], s[i][jj]);
                    s[i][jj] = fmaf(qv[i][2], kk[2][jj], s[i][jj]);
                    s[i][jj] = fmaf(qv[i][3], kk[3][jj], s[i][jj]);
                }
        }

        // Scale + causal mask (diagonal tile only)
        if (j == qt) {
#pragma unroll
            for (int i = 0; i < 4; i++)
#pragma unroll
                for (int jj = 0; jj < 4; jj++) {
                    const int ki = tx * 4 + jj;      // within-tile
                    const int qi = ty * 4 + i;
                    s[i][jj] = (ki <= qi) ? s[i][jj] * scale : -1e30f;
                }
        } else {
#pragma unroll
            for (int i = 0; i < 4; i++)
#pragma unroll
                for (int jj = 0; jj < 4; jj++) s[i][jj] *= scale;
        }

        // Row max (reduce across the 16 lanes sharing a q-row group)
        float mnew[4];
#pragma unroll
        for (int i = 0; i < 4; i++)
            mnew[i] = fmaxf(fmaxf(s[i][0], s[i][1]), fmaxf(s[i][2], s[i][3]));
#pragma unroll
        for (int off = 8; off > 0; off >>= 1) {
#pragma unroll
            for (int i = 0; i < 4; i++)
                mnew[i] = fmaxf(mnew[i], __shfl_xor_sync(0xffffffffu, mnew[i], off, 16));
        }

        float p[4][4], rs[4], al[4];
#pragma unroll
        for (int i = 0; i < 4; i++) {
            const float mt = fmaxf(m_i[i], mnew[i]);
            al[i] = __expf(m_i[i] - mt);
            m_i[i] = mt;
            rs[i] = 0.0f;
#pragma unroll
            for (int jj = 0; jj < 4; jj++) {
                p[i][jj] = __expf(s[i][jj] - mt);
                rs[i] += p[i][jj];
            }
        }
#pragma unroll
        for (int off = 8; off > 0; off >>= 1) {
#pragma unroll
            for (int i = 0; i < 4; i++)
                rs[i] += __shfl_xor_sync(0xffffffffu, rs[i], off, 16);
        }
#pragma unroll
        for (int i = 0; i < 4; i++) {
            l_i[i] = l_i[i] * al[i] + rs[i];
#pragma unroll
            for (int jj = 0; jj < 4; jj++) acc[i][jj] *= al[i];
        }

        __syncthreads();  // all S reads of KsP done before overwriting with P
#pragma unroll
        for (int i = 0; i < 4; i++) {
            float4 pw;
            pw.x = p[i][0]; pw.y = p[i][1]; pw.z = p[i][2]; pw.w = p[i][3];
            *(float4*)&KsP[ty * 4 + i][tx * 4] = pw;
        }
        __syncthreads();

        // O += P @ V  (4x4 per thread; d-cols = tx*4..)
#pragma unroll
        for (int k = 0; k < 64; k += 4) {
            float pv[4][4], vv[4][4];
#pragma unroll
            for (int i = 0; i < 4; i++)
                *(float4*)pv[i] = *(const float4*)&KsP[ty * 4 + i][k];
#pragma unroll
            for (int kk2 = 0; kk2 < 4; kk2++)
                *(float4*)vv[kk2] = *(const float4*)&Vs[k + kk2][tx * 4];
#pragma unroll
            for (int i = 0; i < 4; i++)
#pragma unroll
                for (int jj = 0; jj < 4; jj++) {
                    acc[i][jj] = fmaf(pv[i][0], vv[0][jj], acc[i][jj]);
                    acc[i][jj] = fmaf(pv[i][1], vv[1][jj], acc[i][jj]);
                    acc[i][jj] = fmaf(pv[i][2], vv[2][jj], acc[i][jj]);
                    acc[i][jj] = fmaf(pv[i][3], vv[3][jj], acc[i][jj]);
                }
        }
    }

    // Finalize: O /= l, write [B*T, 1024] (heads concatenated)
    float* Ob = O + base + (size_t)q0 * EMBED;
#pragma unroll
    for (int i = 0; i < 4; i++) {
        const float inv = 1.0f / l_i[i];
        float4 o;
        o.x = acc[i][0] * inv;
        o.y = acc[i][1] * inv;
        o.z = acc[i][2] * inv;
        o.w = acc[i][3] * inv;
        *(float4*)(Ob + (size_t)(ty * 4 + i) * EMBED + tx * 4) = o;
    }
}

// ---------------------------------------------------------------------------
// Launch
// ---------------------------------------------------------------------------
extern "C" void kernel_launch(void* const* d_in, const int* in_sizes, int n_in,
                              void* d_out, int out_size)
{
    (void)in_sizes; (void)n_in; (void)out_size;
    const float* x  = (const float*)d_in[0];
    const float* Wq = (const float*)d_in[1];
    const float* bq = (const float*)d_in[2];
    const float* Wk = (const float*)d_in[3];
    const float* bk = (const float*)d_in[4];
    const float* Wv = (const float*)d_in[5];
    const float* bv = (const float*)d_in[6];
    const float* Wo = (const float*)d_in[7];
    const float* bo = (const float*)d_in[8];
    float* out = (float*)d_out;

    void *pq = nullptr, *pk = nullptr, *pv = nullptr, *pa = nullptr;
    cudaGetSymbolAddress(&pq, g_Q);
    cudaGetSymbolAddress(&pk, g_K);
    cudaGetSymbolAddress(&pv, g_V);
    cudaGetSymbolAddress(&pa, g_A);
    float* Qp = (float*)pq;
    float* Kp = (float*)pk;
    float* Vp = (float*)pv;
    float* Ap = (float*)pa;

    dim3 blk(256);

    // Fused QKV projection: grid.z selects W/bias/dest
    dim3 g1(EMBED / 128, NTOK / 128, 3);   // (8, 32, 3)
    sgemm_bias3<<<g1, blk>>>(x, Wq, Wk, Wv, bq, bk, bv, Qp, Kp, Vp);

    // Causal flash attention
    dim3 g2(TSEQ / 64, NH, 2);             // (32, 16, 2)
    flash_attn<<<g2, blk>>>(Qp, Kp, Vp, Ap);

    // Output projection
    dim3 g3(EMBED / 128, NTOK / 128, 1);   // (8, 32, 1)
    sgemm_bias3<<<g3, blk>>>(Ap, Wo, Wo, Wo, bo, bo, bo, out, out, out);
}

// round 5
// speedup vs baseline: 1.3545x; 1.3545x over previous
#include <cuda_runtime.h>
#include <cuda_bf16.h>
#include <math.h>
#include <stdint.h>

// Problem constants
#define NTOK  4096      // B*T
#define TSEQ  2048
#define EMBED 1024
#define NH    16
#define HDIM  64

// ---------------------------------------------------------------------------
// Scratch (device globals: allocation-free per harness rules)
// ---------------------------------------------------------------------------
__device__ float g_Q[(size_t)NTOK * EMBED];
__device__ float g_K[(size_t)NTOK * EMBED];
__device__ float g_V[(size_t)NTOK * EMBED];
__device__ __nv_bfloat16 g_xhi[(size_t)NTOK * EMBED];
__device__ __nv_bfloat16 g_xlo[(size_t)NTOK * EMBED];
__device__ __nv_bfloat16 g_ahi[(size_t)NTOK * EMBED];
__device__ __nv_bfloat16 g_alo[(size_t)NTOK * EMBED];
__device__ __nv_bfloat16 g_whi[(size_t)4 * EMBED * EMBED];  // Wq^T,Wk^T,Wv^T,Wo^T
__device__ __nv_bfloat16 g_wlo[(size_t)4 * EMBED * EMBED];

// ---------------------------------------------------------------------------
// PTX helpers: ldmatrix + mma.sync (compute_103-safe: no tcgen05)
// ---------------------------------------------------------------------------
__device__ __forceinline__ uint32_t smem_u32(const void* p) {
    uint32_t a;
    asm("{ .reg .u64 t; cvta.to.shared.u64 t, %1; cvt.u32.u64 %0, t; }"
        : "=r"(a) : "l"(p));
    return a;
}

__device__ __forceinline__ void ldsm_x4(uint32_t addr, uint32_t& r0, uint32_t& r1,
                                        uint32_t& r2, uint32_t& r3) {
    asm volatile("ldmatrix.sync.aligned.m8n8.x4.shared.b16 {%0,%1,%2,%3}, [%4];"
                 : "=r"(r0), "=r"(r1), "=r"(r2), "=r"(r3) : "r"(addr));
}

__device__ __forceinline__ void mma16816(float* d, const uint32_t* a,
                                         const uint32_t* b) {
    asm volatile(
        "mma.sync.aligned.m16n8k16.row.col.f32.bf16.bf16.f32 "
        "{%0,%1,%2,%3}, {%4,%5,%6,%7}, {%8,%9}, {%0,%1,%2,%3};"
        : "+f"(d[0]), "+f"(d[1]), "+f"(d[2]), "+f"(d[3])
        : "r"(a[0]), "r"(a[1]), "r"(a[2]), "r"(a[3]), "r"(b[0]), "r"(b[1]));
}

// ---------------------------------------------------------------------------
// fp32 -> (bf16 hi, bf16 lo) split
// ---------------------------------------------------------------------------
__device__ __forceinline__ void split_bf16(float v, __nv_bfloat16& h, __nv_bfloat16& l) {
    h = __float2bfloat16(v);
    l = __float2bfloat16(v - __bfloat162float(h));
}

// ---------------------------------------------------------------------------
// Kernel 1: x -> xhi/xlo
// ---------------------------------------------------------------------------
__global__ __launch_bounds__(256)
void conv_x(const float* __restrict__ x, __nv_bfloat16* __restrict__ xhi,
            __nv_bfloat16* __restrict__ xlo)
{
    size_t i = ((size_t)blockIdx.x * 256 + threadIdx.x) * 4;
    float4 v = *(const float4*)(x + i);
    __nv_bfloat16 h0, h1, h2, h3, l0, l1, l2, l3;
    split_bf16(v.x, h0, l0); split_bf16(v.y, h1, l1);
    split_bf16(v.z, h2, l2); split_bf16(v.w, h3, l3);
    uint2 ph, pl;
    ph.x = (uint32_t)__bfloat16_as_ushort(h0) | ((uint32_t)__bfloat16_as_ushort(h1) << 16);
    ph.y = (uint32_t)__bfloat16_as_ushort(h2) | ((uint32_t)__bfloat16_as_ushort(h3) << 16);
    pl.x = (uint32_t)__bfloat16_as_ushort(l0) | ((uint32_t)__bfloat16_as_ushort(l1) << 16);
    pl.y = (uint32_t)__bfloat16_as_ushort(l2) | ((uint32_t)__bfloat16_as_ushort(l3) << 16);
    *(uint2*)(xhi + i) = ph;
    *(uint2*)(xlo + i) = pl;
}

// ---------------------------------------------------------------------------
// Kernel 2: W [K,N] fp32 -> W^T [N,K] bf16 hi/lo (z selects among 4 weights)
// ---------------------------------------------------------------------------
__global__ __launch_bounds__(256)
void conv_wT(const float* __restrict__ W0, const float* __restrict__ W1,
             const float* __restrict__ W2, const float* __restrict__ W3,
             __nv_bfloat16* __restrict__ whi, __nv_bfloat16* __restrict__ wlo)
{
    __shared__ float tile[32][33];
    const float* W = W0;
    if (blockIdx.z == 1) W = W1;
    else if (blockIdx.z == 2) W = W2;
    else if (blockIdx.z == 3) W = W3;

    const int x = blockIdx.x * 32 + threadIdx.x;   // n (input col)
    const int y = blockIdx.y * 32 + threadIdx.y;   // k (input row)
#pragma unroll
    for (int j = 0; j < 32; j += 8)
        tile[threadIdx.y + j][threadIdx.x] = W[(size_t)(y + j) * EMBED + x];
    __syncthreads();

    const int xo = blockIdx.y * 32 + threadIdx.x;  // k (output col)
    const int yo = blockIdx.x * 32 + threadIdx.y;  // n (output row)
    const size_t zo = (size_t)blockIdx.z * EMBED * EMBED;
#pragma unroll
    for (int j = 0; j < 32; j += 8) {
        float v = tile[threadIdx.x][threadIdx.y + j];
        __nv_bfloat16 h, l;
        split_bf16(v, h, l);
        whi[zo + (size_t)(yo + j) * EMBED + xo] = h;
        wlo[zo + (size_t)(yo + j) * EMBED + xo] = l;
    }
}

// ---------------------------------------------------------------------------
// Kernel 3: bf16x3 GEMM on mma.sync.m16n8k16
//   D[m,n] = sum_k A[m,k]*B[n,k] + bias[n]
//   A: [4096,1024] bf16 hi/lo, B: [1024,1024] (N,K) bf16 hi/lo, D fp32.
//   CTA tile 128x128, BK=32, 8 warps (2x4), warp tile 64x32.
//   SMEM rows padded to 40 bf16 (80 B) -> conflict-free ldmatrix.
// ---------------------------------------------------------------------------
#define TSTR 40   // padded k-stride (bf16 elems)

__device__ __forceinline__ void ld_tile(__nv_bfloat16* s,
                                        const __nv_bfloat16* __restrict__ g,
                                        int tid)
{
#pragma unroll
    for (int it = 0; it < 2; it++) {
        const int c   = tid + it * 256;       // 0..511 chunks of 8 bf16
        const int r   = c >> 2;               // 0..127
        const int col = (c & 3) << 3;         // 0,8,16,24
        uint4 v = *(const uint4*)(g + (size_t)r * EMBED + col);
        *(uint4*)(s + r * TSTR + col) = v;
    }
}

__global__ __launch_bounds__(256, 1)
void gemm_mma(const __nv_bfloat16* __restrict__ Ahi, const __nv_bfloat16* __restrict__ Alo,
              const __nv_bfloat16* __restrict__ Bh0, const __nv_bfloat16* __restrict__ Bh1,
              const __nv_bfloat16* __restrict__ Bh2,
              const __nv_bfloat16* __restrict__ Bl0, const __nv_bfloat16* __restrict__ Bl1,
              const __nv_bfloat16* __restrict__ Bl2,
              const float* __restrict__ c0, const float* __restrict__ c1,
              const float* __restrict__ c2,
              float* __restrict__ D0, float* __restrict__ D1, float* __restrict__ D2)
{
    __shared__ __align__(16) __nv_bfloat16 sAh[128 * TSTR];
    __shared__ __align__(16) __nv_bfloat16 sAl[128 * TSTR];
    __shared__ __align__(16) __nv_bfloat16 sBh[128 * TSTR];
    __shared__ __align__(16) __nv_bfloat16 sBl[128 * TSTR];

    const __nv_bfloat16* Bhi = Bh0;
    const __nv_bfloat16* Blo = Bl0;
    const float* bias = c0;
    float* D = D0;
    if (blockIdx.z == 1)      { Bhi = Bh1; Blo = Bl1; bias = c1; D = D1; }
    else if (blockIdx.z == 2) { Bhi = Bh2; Blo = Bl2; bias = c2; D = D2; }

    const int tid    = threadIdx.x;
    const int lane   = tid & 31;
    const int wid    = tid >> 5;
    const int warp_m = wid >> 2;          // 0..1
    const int warp_n = wid & 3;           // 0..3
    const int bm     = blockIdx.y * 128;
    const int bn     = blockIdx.x * 128;

    // ldmatrix per-lane base addresses (byte offsets into SMEM)
    // A: lanes 0-15 -> rows base+lane, col ks*16; lanes 16-31 -> rows base+(lane-16), col+8
    const uint32_t aRow = warp_m * 64 + (lane & 15);
    const uint32_t aOff = aRow * (TSTR * 2) + ((lane >> 4) << 4);
    const uint32_t aHb  = smem_u32(sAh) + aOff;
    const uint32_t aLb  = smem_u32(sAl) + aOff;
    // B: g = lane>>3: row(n) = warp_n*32 + ((g>>1)<<3) + (lane&7); col(k) = (g&1)*8
    const uint32_t bg   = lane >> 3;
    const uint32_t bRow = warp_n * 32 + ((bg >> 1) << 3) + (lane & 7);
    const uint32_t bOff = bRow * (TSTR * 2) + ((bg & 1) << 4);
    const uint32_t bHb  = smem_u32(sBh) + bOff;
    const uint32_t bLb  = smem_u32(sBl) + bOff;

    float acc[4][4][4];
#pragma unroll
    for (int i = 0; i < 4; i++)
#pragma unroll
        for (int j = 0; j < 4; j++)
#pragma unroll
            for (int q = 0; q < 4; q++) acc[i][j][q] = 0.0f;

    const __nv_bfloat16* gAh = Ahi + (size_t)bm * EMBED;
    const __nv_bfloat16* gAl = Alo + (size_t)bm * EMBED;
    const __nv_bfloat16* gBh = Bhi + (size_t)bn * EMBED;
    const __nv_bfloat16* gBl = Blo + (size_t)bn * EMBED;

    for (int kb = 0; kb < EMBED / 32; kb++) {
        __syncthreads();
        const int kc = kb * 32;
        ld_tile(sAh, gAh + kc, tid);
        ld_tile(sAl, gAl + kc, tid);
        ld_tile(sBh, gBh + kc, tid);
        ld_tile(sBl, gBl + kc, tid);
        __syncthreads();

#pragma unroll
        for (int ks = 0; ks < 2; ks++) {
            uint32_t ah[4][4], al[4][4], bh[4][2], bl[4][2];
#pragma unroll
            for (int mi = 0; mi < 4; mi++) {
                const uint32_t d = mi * (16 * TSTR * 2) + ks * 32;
                ldsm_x4(aHb + d, ah[mi][0], ah[mi][1], ah[mi][2], ah[mi][3]);
                ldsm_x4(aLb + d, al[mi][0], al[mi][1], al[mi][2], al[mi][3]);
            }
#pragma unroll
            for (int np = 0; np < 2; np++) {
                const uint32_t d = np * (16 * TSTR * 2) + ks * 32;
                ldsm_x4(bHb + d, bh[np*2][0], bh[np*2][1], bh[np*2+1][0], bh[np*2+1][1]);
                ldsm_x4(bLb + d, bl[np*2][0], bl[np*2][1], bl[np*2+1][0], bl[np*2+1][1]);
            }
#pragma unroll
            for (int mi = 0; mi < 4; mi++)
#pragma unroll
                for (int ni = 0; ni < 4; ni++) {
                    mma16816(acc[mi][ni], ah[mi], bh[ni]);
                    mma16816(acc[mi][ni], ah[mi], bl[ni]);
                    mma16816(acc[mi][ni], al[mi], bh[ni]);
                }
        }
    }

    // Epilogue: acc frag (mi,ni): c0,c1 at (row, col..col+1), c2,c3 at (row+8)
#pragma unroll
    for (int ni = 0; ni < 4; ni++) {
        const int col = bn + warp_n * 32 + ni * 8 + ((lane & 3) << 1);
        const float2 bv = *(const float2*)(bias + col);
#pragma unroll
        for (int mi = 0; mi < 4; mi++) {
            const int row = bm + warp_m * 64 + mi * 16 + (lane >> 2);
            float2 o0, o1;
            o0.x = acc[mi][ni][0] + bv.x;
            o0.y = acc[mi][ni][1] + bv.y;
            o1.x = acc[mi][ni][2] + bv.x;
            o1.y = acc[mi][ni][3] + bv.y;
            *(float2*)(D + (size_t)row * EMBED + col)       = o0;
            *(float2*)(D + (size_t)(row + 8) * EMBED + col) = o1;
        }
    }
}

// ---------------------------------------------------------------------------
// Flash attention (causal), fp32; epilogue writes bf16 hi/lo split.
// q-tiles scheduled heavy-first (reversed) for better wave packing.
// ---------------------------------------------------------------------------
__device__ __forceinline__ int ksw(int d, int kslot) {
    return kslot ^ ((d >> 2) & 15) ^ ((d & 3) << 2);
}

__global__ __launch_bounds__(256, 2)
void flash_attn(const float* __restrict__ Q, const float* __restrict__ K,
                const float* __restrict__ V,
                __nv_bfloat16* __restrict__ Ohi, __nv_bfloat16* __restrict__ Olo)
{
    __shared__ float Qs[64][HDIM];
    __shared__ float KsP[64][64];
    __shared__ float Vs[64][HDIM];

    const int tid = threadIdx.x;
    const int tx  = tid & 15;
    const int ty  = tid >> 4;
    const int qt  = gridDim.x - 1 - blockIdx.x;   // heavy tiles first
    const int h   = blockIdx.y;
    const int b   = blockIdx.z;

    const size_t base = (size_t)b * TSEQ * EMBED + (size_t)h * HDIM;
    const int q0 = qt * 64;

    {
        const float* Qb = Q + base + (size_t)q0 * EMBED;
#pragma unroll
        for (int it = 0; it < 4; it++) {
            const int i = tid + it * 256;
            const int r = i >> 4;
            const int c = (i & 15) << 2;
            *(float4*)&Qs[r][c] = *(const float4*)(Qb + (size_t)r * EMBED + c);
        }
    }

    float acc[4][4];
    float m_i[4], l_i[4];
#pragma unroll
    for (int i = 0; i < 4; i++) {
        m_i[i] = -1e30f; l_i[i] = 0.0f;
#pragma unroll
        for (int j = 0; j < 4; j++) acc[i][j] = 0.0f;
    }

    const float scale = 0.125f;

    for (int j = 0; j <= qt; j++) {
        const float* Kb = K + base + (size_t)(j * 64) * EMBED;
        const float* Vb = V + base + (size_t)(j * 64) * EMBED;

        __syncthreads();
#pragma unroll
        for (int it = 0; it < 4; it++) {
            const int i = tid + it * 256;
            const int r = i >> 4;
            const int c = (i & 15) << 2;
            float4 kv = *(const float4*)(Kb + (size_t)r * EMBED + c);
            KsP[c + 0][(ksw(c + 0, r >> 2) << 2) + (r & 3)] = kv.x;
            KsP[c + 1][(ksw(c + 1, r >> 2) << 2) + (r & 3)] = kv.y;
            KsP[c + 2][(ksw(c + 2, r >> 2) << 2) + (r & 3)] = kv.z;
            KsP[c + 3][(ksw(c + 3, r >> 2) << 2) + (r & 3)] = kv.w;
            *(float4*)&Vs[r][c] = *(const float4*)(Vb + (size_t)r * EMBED + c);
        }
        __syncthreads();

        float s[4][4];
#pragma unroll
        for (int i = 0; i < 4; i++)
#pragma unroll
            for (int jj = 0; jj < 4; jj++) s[i][jj] = 0.0f;

#pragma unroll
        for (int d = 0; d < HDIM; d += 4) {
            float qv[4][4], kk[4][4];
#pragma unroll
            for (int i = 0; i < 4; i++)
                *(float4*)qv[i] = *(const float4*)&Qs[ty * 4 + i][d];
#pragma unroll
            for (int dd = 0; dd < 4; dd++)
                *(float4*)kk[dd] = *(const float4*)&KsP[d + dd][ksw(d + dd, tx) << 2];
#pragma unroll
            for (int i = 0; i < 4; i++)
#pragma unroll
                for (int jj = 0; jj < 4; jj++) {
                    s[i][jj] = fmaf(qv[i][0], kk[0][jj], s[i][jj]);
                    s[i][jj] = fmaf(qv[i][1], kk[1][jj], s[i][jj]);
                    s[i][jj] = fmaf(qv[i][2], kk[2][jj], s[i][jj]);
                    s[i][jj] = fmaf(qv[i][3], kk[3][jj], s[i][jj]);
                }
        }

        if (j == qt) {
#pragma unroll
            for (int i = 0; i < 4; i++)
#pragma unroll
                for (int jj = 0; jj < 4; jj++) {
                    const int ki = tx * 4 + jj;
                    const int qi = ty * 4 + i;
                    s[i][jj] = (ki <= qi) ? s[i][jj] * scale : -1e30f;
                }
        } else {
#pragma unroll
            for (int i = 0; i < 4; i++)
#pragma unroll
                for (int jj = 0; jj < 4; jj++) s[i][jj] *= scale;
        }

        float mnew[4];
#pragma unroll
        for (int i = 0; i < 4; i++)
            mnew[i] = fmaxf(fmaxf(s[i][0], s[i][1]), fmaxf(s[i][2], s[i][3]));
#pragma unroll
        for (int off = 8; off > 0; off >>= 1) {
#pragma unroll
            for (int i = 0; i < 4; i++)
                mnew[i] = fmaxf(mnew[i], __shfl_xor_sync(0xffffffffu, mnew[i], off, 16));
        }

        float p[4][4], rs[4], al[4];
#pragma unroll
        for (int i = 0; i < 4; i++) {
            const float mt = fmaxf(m_i[i], mnew[i]);
            al[i] = __expf(m_i[i] - mt);
            m_i[i] = mt;
            rs[i] = 0.0f;
#pragma unroll
            for (int jj = 0; jj < 4; jj++) {
                p[i][jj] = __expf(s[i][jj] - mt);
                rs[i] += p[i][jj];
            }
        }
#pragma unroll
        for (int off = 8; off > 0; off >>= 1) {
#pragma unroll
            for (int i = 0; i < 4; i++)
                rs[i] += __shfl_xor_sync(0xffffffffu, rs[i], off, 16);
        }
#pragma unroll
        for (int i = 0; i < 4; i++) {
            l_i[i] = l_i[i] * al[i] + rs[i];
#pragma unroll
            for (int jj = 0; jj < 4; jj++) acc[i][jj] *= al[i];
        }

        __syncthreads();
#pragma unroll
        for (int i = 0; i < 4; i++) {
            float4 pw;
            pw.x = p[i][0]; pw.y = p[i][1]; pw.z = p[i][2]; pw.w = p[i][3];
            *(float4*)&KsP[ty * 4 + i][tx * 4] = pw;
        }
        __syncthreads();

#pragma unroll
        for (int k = 0; k < 64; k += 4) {
            float pv[4][4], vv[4][4];
#pragma unroll
            for (int i = 0; i < 4; i++)
                *(float4*)pv[i] = *(const float4*)&KsP[ty * 4 + i][k];
#pragma unroll
            for (int kk2 = 0; kk2 < 4; kk2++)
                *(float4*)vv[kk2] = *(const float4*)&Vs[k + kk2][tx * 4];
#pragma unroll
            for (int i = 0; i < 4; i++)
#pragma unroll
                for (int jj = 0; jj < 4; jj++) {
                    acc[i][jj] = fmaf(pv[i][0], vv[0][jj], acc[i][jj]);
                    acc[i][jj] = fmaf(pv[i][1], vv[1][jj], acc[i][jj]);
                    acc[i][jj] = fmaf(pv[i][2], vv[2][jj], acc[i][jj]);
                    acc[i][jj] = fmaf(pv[i][3], vv[3][jj], acc[i][jj]);
                }
        }
    }

    // Finalize: O /= l, write bf16 hi/lo split (feeds bf16x3 O-projection)
#pragma unroll
    for (int i = 0; i < 4; i++) {
        const float inv = 1.0f / l_i[i];
        const size_t off = base + (size_t)(q0 + ty * 4 + i) * EMBED + tx * 4;
        __nv_bfloat16 h0, h1, h2, h3, l0, l1, l2, l3;
        split_bf16(acc[i][0] * inv, h0, l0);
        split_bf16(acc[i][1] * inv, h1, l1);
        split_bf16(acc[i][2] * inv, h2, l2);
        split_bf16(acc[i][3] * inv, h3, l3);
        uint2 ph, pl;
        ph.x = (uint32_t)__bfloat16_as_ushort(h0) | ((uint32_t)__bfloat16_as_ushort(h1) << 16);
        ph.y = (uint32_t)__bfloat16_as_ushort(h2) | ((uint32_t)__bfloat16_as_ushort(h3) << 16);
        pl.x = (uint32_t)__bfloat16_as_ushort(l0) | ((uint32_t)__bfloat16_as_ushort(l1) << 16);
        pl.y = (uint32_t)__bfloat16_as_ushort(l2) | ((uint32_t)__bfloat16_as_ushort(l3) << 16);
        *(uint2*)(Ohi + off) = ph;
        *(uint2*)(Olo + off) = pl;
    }
}

// ---------------------------------------------------------------------------
// Launch
// ---------------------------------------------------------------------------
extern "C" void kernel_launch(void* const* d_in, const int* in_sizes, int n_in,
                              void* d_out, int out_size)
{
    (void)in_sizes; (void)n_in; (void)out_size;
    const float* x  = (const float*)d_in[0];
    const float* Wq = (const float*)d_in[1];
    const float* bq = (const float*)d_in[2];
    const float* Wk = (const float*)d_in[3];
    const float* bk = (const float*)d_in[4];
    const float* Wv = (const float*)d_in[5];
    const float* bv = (const float*)d_in[6];
    const float* Wo = (const float*)d_in[7];
    const float* bo = (const float*)d_in[8];
    float* out = (float*)d_out;

    void *pq, *pk, *pv, *pxh, *pxl, *pah, *pal, *pwh, *pwl;
    cudaGetSymbolAddress(&pq,  g_Q);
    cudaGetSymbolAddress(&pk,  g_K);
    cudaGetSymbolAddress(&pv,  g_V);
    cudaGetSymbolAddress(&pxh, g_xhi);
    cudaGetSymbolAddress(&pxl, g_xlo);
    cudaGetSymbolAddress(&pah, g_ahi);
    cudaGetSymbolAddress(&pal, g_alo);
    cudaGetSymbolAddress(&pwh, g_whi);
    cudaGetSymbolAddress(&pwl, g_wlo);
    float* Qp = (float*)pq;
    float* Kp = (float*)pk;
    float* Vp = (float*)pv;
    __nv_bfloat16* xhi = (__nv_bfloat16*)pxh;
    __nv_bfloat16* xlo = (__nv_bfloat16*)pxl;
    __nv_bfloat16* ahi = (__nv_bfloat16*)pah;
    __nv_bfloat16* alo = (__nv_bfloat16*)pal;
    __nv_bfloat16* whi = (__nv_bfloat16*)pwh;
    __nv_bfloat16* wlo = (__nv_bfloat16*)pwl;

    const size_t WSZ = (size_t)EMBED * EMBED;

    // 1) fp32 -> bf16 hi/lo conversions
    conv_x<<<(NTOK * EMBED) / (256 * 4), 256>>>(x, xhi, xlo);
    conv_wT<<<dim3(32, 32, 4), dim3(32, 8)>>>(Wq, Wk, Wv, Wo, whi, wlo);

    // 2) fused QKV projection on tensor cores (z selects W/bias/dest)
    dim3 g1(EMBED / 128, NTOK / 128, 3);
    gemm_mma<<<g1, 256>>>(xhi, xlo,
                          whi, whi + WSZ, whi + 2 * WSZ,
                          wlo, wlo + WSZ, wlo + 2 * WSZ,
                          bq, bk, bv, Qp, Kp, Vp);

    // 3) causal flash attention (fp32), epilogue emits bf16 hi/lo
    dim3 g2(TSEQ / 64, NH, 2);
    flash_attn<<<g2, 256>>>(Qp, Kp, Vp, ahi, alo);

    // 4) output projection on tensor cores
    dim3 g3(EMBED / 128, NTOK / 128, 1);
    gemm_mma<<<g3, 256>>>(ahi, alo,
                          whi + 3 * WSZ, whi + 3 * WSZ, whi + 3 * WSZ,
                          wlo + 3 * WSZ, wlo + 3 * WSZ, wlo + 3 * WSZ,
                          bo, bo, bo, out, out, out);
}

// round 6
// speedup vs baseline: 1.3623x; 1.0058x over previous
#include <cuda_runtime.h>
#include <cuda_bf16.h>
#include <math.h>
#include <stdint.h>

// Problem constants
#define NTOK  4096      // B*T
#define TSEQ  2048
#define EMBED 1024
#define NH    16
#define HDIM  64

// ---------------------------------------------------------------------------
// Scratch (device globals: allocation-free per harness rules)
// ---------------------------------------------------------------------------
__device__ float g_Q[(size_t)NTOK * EMBED];
__device__ float g_K[(size_t)NTOK * EMBED];
__device__ float g_V[(size_t)NTOK * EMBED];
__device__ __nv_bfloat16 g_xhi[(size_t)NTOK * EMBED];
__device__ __nv_bfloat16 g_xlo[(size_t)NTOK * EMBED];
__device__ __nv_bfloat16 g_ahi[(size_t)NTOK * EMBED];
__device__ __nv_bfloat16 g_alo[(size_t)NTOK * EMBED];
__device__ __nv_bfloat16 g_whi[(size_t)4 * EMBED * EMBED];  // Wq^T,Wk^T,Wv^T,Wo^T
__device__ __nv_bfloat16 g_wlo[(size_t)4 * EMBED * EMBED];

// ---------------------------------------------------------------------------
// PTX helpers: ldmatrix + mma.sync (compute_103-safe: no tcgen05)
// ---------------------------------------------------------------------------
__device__ __forceinline__ uint32_t smem_u32(const void* p) {
    uint32_t a;
    asm("{ .reg .u64 t; cvta.to.shared.u64 t, %1; cvt.u32.u64 %0, t; }"
        : "=r"(a) : "l"(p));
    return a;
}

__device__ __forceinline__ void ldsm_x4(uint32_t addr, uint32_t& r0, uint32_t& r1,
                                        uint32_t& r2, uint32_t& r3) {
    asm volatile("ldmatrix.sync.aligned.m8n8.x4.shared.b16 {%0,%1,%2,%3}, [%4];"
                 : "=r"(r0), "=r"(r1), "=r"(r2), "=r"(r3) : "r"(addr));
}

__device__ __forceinline__ void mma16816(float* d, const uint32_t* a,
                                         const uint32_t* b) {
    asm volatile(
        "mma.sync.aligned.m16n8k16.row.col.f32.bf16.bf16.f32 "
        "{%0,%1,%2,%3}, {%4,%5,%6,%7}, {%8,%9}, {%0,%1,%2,%3};"
        : "+f"(d[0]), "+f"(d[1]), "+f"(d[2]), "+f"(d[3])
        : "r"(a[0]), "r"(a[1]), "r"(a[2]), "r"(a[3]), "r"(b[0]), "r"(b[1]));
}

// ---------------------------------------------------------------------------
// fp32 -> (bf16 hi, bf16 lo) split
// ---------------------------------------------------------------------------
__device__ __forceinline__ void split_bf16(float v, __nv_bfloat16& h, __nv_bfloat16& l) {
    h = __float2bfloat16(v);
    l = __float2bfloat16(v - __bfloat162float(h));
}

// ---------------------------------------------------------------------------
// Kernel 1: x -> xhi/xlo
// ---------------------------------------------------------------------------
__global__ __launch_bounds__(256)
void conv_x(const float* __restrict__ x, __nv_bfloat16* __restrict__ xhi,
            __nv_bfloat16* __restrict__ xlo)
{
    size_t i = ((size_t)blockIdx.x * 256 + threadIdx.x) * 4;
    float4 v = *(const float4*)(x + i);
    __nv_bfloat16 h0, h1, h2, h3, l0, l1, l2, l3;
    split_bf16(v.x, h0, l0); split_bf16(v.y, h1, l1);
    split_bf16(v.z, h2, l2); split_bf16(v.w, h3, l3);
    uint2 ph, pl;
    ph.x = (uint32_t)__bfloat16_as_ushort(h0) | ((uint32_t)__bfloat16_as_ushort(h1) << 16);
    ph.y = (uint32_t)__bfloat16_as_ushort(h2) | ((uint32_t)__bfloat16_as_ushort(h3) << 16);
    pl.x = (uint32_t)__bfloat16_as_ushort(l0) | ((uint32_t)__bfloat16_as_ushort(l1) << 16);
    pl.y = (uint32_t)__bfloat16_as_ushort(l2) | ((uint32_t)__bfloat16_as_ushort(l3) << 16);
    *(uint2*)(xhi + i) = ph;
    *(uint2*)(xlo + i) = pl;
}

// ---------------------------------------------------------------------------
// Kernel 2: W [K,N] fp32 -> W^T [N,K] bf16 hi/lo (z selects among 4 weights)
// ---------------------------------------------------------------------------
__global__ __launch_bounds__(256)
void conv_wT(const float* __restrict__ W0, const float* __restrict__ W1,
             const float* __restrict__ W2, const float* __restrict__ W3,
             __nv_bfloat16* __restrict__ whi, __nv_bfloat16* __restrict__ wlo)
{
    __shared__ float tile[32][33];
    const float* W = W0;
    if (blockIdx.z == 1) W = W1;
    else if (blockIdx.z == 2) W = W2;
    else if (blockIdx.z == 3) W = W3;

    const int x = blockIdx.x * 32 + threadIdx.x;   // n (input col)
    const int y = blockIdx.y * 32 + threadIdx.y;   // k (input row)
#pragma unroll
    for (int j = 0; j < 32; j += 8)
        tile[threadIdx.y + j][threadIdx.x] = W[(size_t)(y + j) * EMBED + x];
    __syncthreads();

    const int xo = blockIdx.y * 32 + threadIdx.x;  // k (output col)
    const int yo = blockIdx.x * 32 + threadIdx.y;  // n (output row)
    const size_t zo = (size_t)blockIdx.z * EMBED * EMBED;
#pragma unroll
    for (int j = 0; j < 32; j += 8) {
        float v = tile[threadIdx.x][threadIdx.y + j];
        __nv_bfloat16 h, l;
        split_bf16(v, h, l);
        whi[zo + (size_t)(yo + j) * EMBED + xo] = h;
        wlo[zo + (size_t)(yo + j) * EMBED + xo] = l;
    }
}

// ---------------------------------------------------------------------------
// Kernel 3: bf16x3 GEMM on mma.sync.m16n8k16
//   D[m,n] = sum_k A[m,k]*B[n,k] + bias[n]
//   A: [4096,1024] bf16 hi/lo, B: [1024,1024] (N,K) bf16 hi/lo, D fp32.
//   CTA tile 128x128, BK=32, 8 warps (2x4), warp tile 64x32.
//   SMEM rows padded to 40 bf16 (80 B) -> conflict-free ldmatrix.
// ---------------------------------------------------------------------------
#define TSTR 40   // padded k-stride (bf16 elems)

__device__ __forceinline__ void ld_tile(__nv_bfloat16* s,
                                        const __nv_bfloat16* __restrict__ g,
                                        int tid)
{
#pragma unroll
    for (int it = 0; it < 2; it++) {
        const int c   = tid + it * 256;       // 0..511 chunks of 8 bf16
        const int r   = c >> 2;               // 0..127
        const int col = (c & 3) << 3;         // 0,8,16,24
        uint4 v = *(const uint4*)(g + (size_t)r * EMBED + col);
        *(uint4*)(s + r * TSTR + col) = v;
    }
}

__global__ __launch_bounds__(256, 1)
void gemm_mma(const __nv_bfloat16* __restrict__ Ahi, const __nv_bfloat16* __restrict__ Alo,
              const __nv_bfloat16* __restrict__ Bh0, const __nv_bfloat16* __restrict__ Bh1,
              const __nv_bfloat16* __restrict__ Bh2,
              const __nv_bfloat16* __restrict__ Bl0, const __nv_bfloat16* __restrict__ Bl1,
              const __nv_bfloat16* __restrict__ Bl2,
              const float* __restrict__ c0, const float* __restrict__ c1,
              const float* __restrict__ c2,
              float* __restrict__ D0, float* __restrict__ D1, float* __restrict__ D2)
{
    __shared__ __align__(16) __nv_bfloat16 sAh[128 * TSTR];
    __shared__ __align__(16) __nv_bfloat16 sAl[128 * TSTR];
    __shared__ __align__(16) __nv_bfloat16 sBh[128 * TSTR];
    __shared__ __align__(16) __nv_bfloat16 sBl[128 * TSTR];

    const __nv_bfloat16* Bhi = Bh0;
    const __nv_bfloat16* Blo = Bl0;
    const float* bias = c0;
    float* D = D0;
    if (blockIdx.z == 1)      { Bhi = Bh1; Blo = Bl1; bias = c1; D = D1; }
    else if (blockIdx.z == 2) { Bhi = Bh2; Blo = Bl2; bias = c2; D = D2; }

    const int tid    = threadIdx.x;
    const int lane   = tid & 31;
    const int wid    = tid >> 5;
    const int warp_m = wid >> 2;          // 0..1
    const int warp_n = wid & 3;           // 0..3
    const int bm     = blockIdx.y * 128;
    const int bn     = blockIdx.x * 128;

    // ldmatrix per-lane base addresses (byte offsets into SMEM)
    // A: lanes 0-15 -> rows base+lane, col ks*16; lanes 16-31 -> rows base+(lane-16), col+8
    const uint32_t aRow = warp_m * 64 + (lane & 15);
    const uint32_t aOff = aRow * (TSTR * 2) + ((lane >> 4) << 4);
    const uint32_t aHb  = smem_u32(sAh) + aOff;
    const uint32_t aLb  = smem_u32(sAl) + aOff;
    // B: g = lane>>3: row(n) = warp_n*32 + ((g>>1)<<3) + (lane&7); col(k) = (g&1)*8
    const uint32_t bg   = lane >> 3;
    const uint32_t bRow = warp_n * 32 + ((bg >> 1) << 3) + (lane & 7);
    const uint32_t bOff = bRow * (TSTR * 2) + ((bg & 1) << 4);
    const uint32_t bHb  = smem_u32(sBh) + bOff;
    const uint32_t bLb  = smem_u32(sBl) + bOff;

    float acc[4][4][4];
#pragma unroll
    for (int i = 0; i < 4; i++)
#pragma unroll
        for (int j = 0; j < 4; j++)
#pragma unroll
            for (int q = 0; q < 4; q++) acc[i][j][q] = 0.0f;

    const __nv_bfloat16* gAh = Ahi + (size_t)bm * EMBED;
    const __nv_bfloat16* gAl = Alo + (size_t)bm * EMBED;
    const __nv_bfloat16* gBh = Bhi + (size_t)bn * EMBED;
    const __nv_bfloat16* gBl = Blo + (size_t)bn * EMBED;

    for (int kb = 0; kb < EMBED / 32; kb++) {
        __syncthreads();
        const int kc = kb * 32;
        ld_tile(sAh, gAh + kc, tid);
        ld_tile(sAl, gAl + kc, tid);
        ld_tile(sBh, gBh + kc, tid);
        ld_tile(sBl, gBl + kc, tid);
        __syncthreads();

#pragma unroll
        for (int ks = 0; ks < 2; ks++) {
            uint32_t ah[4][4], al[4][4], bh[4][2], bl[4][2];
#pragma unroll
            for (int mi = 0; mi < 4; mi++) {
                const uint32_t d = mi * (16 * TSTR * 2) + ks * 32;
                ldsm_x4(aHb + d, ah[mi][0], ah[mi][1], ah[mi][2], ah[mi][3]);
                ldsm_x4(aLb + d, al[mi][0], al[mi][1], al[mi][2], al[mi][3]);
            }
#pragma unroll
            for (int np = 0; np < 2; np++) {
                const uint32_t d = np * (16 * TSTR * 2) + ks * 32;
                ldsm_x4(bHb + d, bh[np*2][0], bh[np*2][1], bh[np*2+1][0], bh[np*2+1][1]);
                ldsm_x4(bLb + d, bl[np*2][0], bl[np*2][1], bl[np*2+1][0], bl[np*2+1][1]);
            }
#pragma unroll
            for (int mi = 0; mi < 4; mi++)
#pragma unroll
                for (int ni = 0; ni < 4; ni++) {
                    mma16816(acc[mi][ni], ah[mi], bh[ni]);
                    mma16816(acc[mi][ni], ah[mi], bl[ni]);
                    mma16816(acc[mi][ni], al[mi], bh[ni]);
                }
        }
    }

    // Epilogue: acc frag (mi,ni): c0,c1 at (row, col..col+1), c2,c3 at (row+8)
#pragma unroll
    for (int ni = 0; ni < 4; ni++) {
        const int col = bn + warp_n * 32 + ni * 8 + ((lane & 3) << 1);
        const float2 bv = *(const float2*)(bias + col);
#pragma unroll
        for (int mi = 0; mi < 4; mi++) {
            const int row = bm + warp_m * 64 + mi * 16 + (lane >> 2);
            float2 o0, o1;
            o0.x = acc[mi][ni][0] + bv.x;
            o0.y = acc[mi][ni][1] + bv.y;
            o1.x = acc[mi][ni][2] + bv.x;
            o1.y = acc[mi][ni][3] + bv.y;
            *(float2*)(D + (size_t)row * EMBED + col)       = o0;
            *(float2*)(D + (size_t)(row + 8) * EMBED + col) = o1;
        }
    }
}

// ---------------------------------------------------------------------------
// Flash attention (causal), fp32; epilogue writes bf16 hi/lo split.
// q-tiles scheduled heavy-first (reversed) for better wave packing.
// ---------------------------------------------------------------------------
__device__ __forceinline__ int ksw(int d, int kslot) {
    return kslot ^ ((d >> 2) & 15) ^ ((d & 3) << 2);
}

__global__ __launch_bounds__(256, 2)
void flash_attn(const float* __restrict__ Q, const float* __restrict__ K,
                const float* __restrict__ V,
                __nv_bfloat16* __restrict__ Ohi, __nv_bfloat16* __restrict__ Olo)
{
    __shared__ float Qs[64][HDIM];
    __shared__ float KsP[64][64];
    __shared__ float Vs[64][HDIM];

    const int tid = threadIdx.x;
    const int tx  = tid & 15;
    const int ty  = tid >> 4;
    const int qt  = gridDim.x - 1 - blockIdx.x;   // heavy tiles first
    const int h   = blockIdx.y;
    const int b   = blockIdx.z;

    const size_t base = (size_t)b * TSEQ * EMBED + (size_t)h * HDIM;
    const int q0 = qt * 64;

    {
        const float* Qb = Q + base + (size_t)q0 * EMBED;
#pragma unroll
        for (int it = 0; it < 4; it++) {
            const int i = tid + it * 256;
            const int r = i >> 4;
            const int c = (i & 15) << 2;
            *(float4*)&Qs[r][c] = *(const float4*)(Qb + (size_t)r * EMBED + c);
        }
    }

    float acc[4][4];
    float m_i[4], l_i[4];
#pragma unroll
    for (int i = 0; i < 4; i++) {
        m_i[i] = -1e30f; l_i[i] = 0.0f;
#pragma unroll
        for (int j = 0; j < 4; j++) acc[i][j] = 0.0f;
    }

    const float scale = 0.125f;

    for (int j = 0; j <= qt; j++) {
        const float* Kb = K + base + (size_t)(j * 64) * EMBED;
        const float* Vb = V + base + (size_t)(j * 64) * EMBED;

        __syncthreads();
#pragma unroll
        for (int it = 0; it < 4; it++) {
            const int i = tid + it * 256;
            const int r = i >> 4;
            const int c = (i & 15) << 2;
            float4 kv = *(const float4*)(Kb + (size_t)r * EMBED + c);
            KsP[c + 0][(ksw(c + 0, r >> 2) << 2) + (r & 3)] = kv.x;
            KsP[c + 1][(ksw(c + 1, r >> 2) << 2) + (r & 3)] = kv.y;
            KsP[c + 2][(ksw(c + 2, r >> 2) << 2) + (r & 3)] = kv.z;
            KsP[c + 3][(ksw(c + 3, r >> 2) << 2) + (r & 3)] = kv.w;
            *(float4*)&Vs[r][c] = *(const float4*)(Vb + (size_t)r * EMBED + c);
        }
        __syncthreads();

        float s[4][4];
#pragma unroll
        for (int i = 0; i < 4; i++)
#pragma unroll
            for (int jj = 0; jj < 4; jj++) s[i][jj] = 0.0f;

#pragma unroll
        for (int d = 0; d < HDIM; d += 4) {
            float qv[4][4], kk[4][4];
#pragma unroll
            for (int i = 0; i < 4; i++)
                *(float4*)qv[i] = *(const float4*)&Qs[ty * 4 + i][d];
#pragma unroll
            for (int dd = 0; dd < 4; dd++)
                *(float4*)kk[dd] = *(const float4*)&KsP[d + dd][ksw(d + dd, tx) << 2];
#pragma unroll
            for (int i = 0; i < 4; i++)
#pragma unroll
                for (int jj = 0; jj < 4; jj++) {
                    s[i][jj] = fmaf(qv[i][0], kk[0][jj], s[i][jj]);
                    s[i][jj] = fmaf(qv[i][1], kk[1][jj], s[i][jj]);
                    s[i][jj] = fmaf(qv[i][2], kk[2][jj], s[i][jj]);
                    s[i][jj] = fmaf(qv[i][3], kk[3][jj], s[i][jj]);
                }
        }

        if (j == qt) {
#pragma unroll
            for (int i = 0; i < 4; i++)
#pragma unroll
                for (int jj = 0; jj < 4; jj++) {
                    const int ki = tx * 4 + jj;
                    const int qi = ty * 4 + i;
                    s[i][jj] = (ki <= qi) ? s[i][jj] * scale : -1e30f;
                }
        } else {
#pragma unroll
            for (int i = 0; i < 4; i++)
#pragma unroll
                for (int jj = 0; jj < 4; jj++) s[i][jj] *= scale;
        }

        float mnew[4];
#pragma unroll
        for (int i = 0; i < 4; i++)
            mnew[i] = fmaxf(fmaxf(s[i][0], s[i][1]), fmaxf(s[i][2], s[i][3]));
#pragma unroll
        for (int off = 8; off > 0; off >>= 1) {
#pragma unroll
            for (int i = 0; i < 4; i++)
                mnew[i] = fmaxf(mnew[i], __shfl_xor_sync(0xffffffffu, mnew[i], off, 16));
        }

        float p[4][4], rs[4], al[4];
#pragma unroll
        for (int i = 0; i < 4; i++) {
            const float mt = fmaxf(m_i[i], mnew[i]);
            al[i] = __expf(m_i[i] - mt);
            m_i[i] = mt;
            rs[i] = 0.0f;
#pragma unroll
            for (int jj = 0; jj < 4; jj++) {
                p[i][jj] = __expf(s[i][jj] - mt);
                rs[i] += p[i][jj];
            }
        }
#pragma unroll
        for (int off = 8; off > 0; off >>= 1) {
#pragma unroll
            for (int i = 0; i < 4; i++)
                rs[i] += __shfl_xor_sync(0xffffffffu, rs[i], off, 16);
        }
#pragma unroll
        for (int i = 0; i < 4; i++) {
            l_i[i] = l_i[i] * al[i] + rs[i];
#pragma unroll
            for (int jj = 0; jj < 4; jj++) acc[i][jj] *= al[i];
        }

        __syncthreads();
#pragma unroll
        for (int i = 0; i < 4; i++) {
            float4 pw;
            pw.x = p[i][0]; pw.y = p[i][1]; pw.z = p[i][2]; pw.w = p[i][3];
            *(float4*)&KsP[ty * 4 + i][tx * 4] = pw;
        }
        __syncthreads();

#pragma unroll
        for (int k = 0; k < 64; k += 4) {
            float pv[4][4], vv[4][4];
#pragma unroll
            for (int i = 0; i < 4; i++)
                *(float4*)pv[i] = *(const float4*)&KsP[ty * 4 + i][k];
#pragma unroll
            for (int kk2 = 0; kk2 < 4; kk2++)
                *(float4*)vv[kk2] = *(const float4*)&Vs[k + kk2][tx * 4];
#pragma unroll
            for (int i = 0; i < 4; i++)
#pragma unroll
                for (int jj = 0; jj < 4; jj++) {
                    acc[i][jj] = fmaf(pv[i][0], vv[0][jj], acc[i][jj]);
                    acc[i][jj] = fmaf(pv[i][1], vv[1][jj], acc[i][jj]);
                    acc[i][jj] = fmaf(pv[i][2], vv[2][jj], acc[i][jj]);
                    acc[i][jj] = fmaf(pv[i][3], vv[3][jj], acc[i][jj]);
                }
        }
    }

    // Finalize: O /= l, write bf16 hi/lo split (feeds bf16x3 O-projection)
#pragma unroll
    for (int i = 0; i < 4; i++) {
        const float inv = 1.0f / l_i[i];
        const size_t off = base + (size_t)(q0 + ty * 4 + i) * EMBED + tx * 4;
        __nv_bfloat16 h0, h1, h2, h3, l0, l1, l2, l3;
        split_bf16(acc[i][0] * inv, h0, l0);
        split_bf16(acc[i][1] * inv, h1, l1);
        split_bf16(acc[i][2] * inv, h2, l2);
        split_bf16(acc[i][3] * inv, h3, l3);
        uint2 ph, pl;
        ph.x = (uint32_t)__bfloat16_as_ushort(h0) | ((uint32_t)__bfloat16_as_ushort(h1) << 16);
        ph.y = (uint32_t)__bfloat16_as_ushort(h2) | ((uint32_t)__bfloat16_as_ushort(h3) << 16);
        pl.x = (uint32_t)__bfloat16_as_ushort(l0) | ((uint32_t)__bfloat16_as_ushort(l1) << 16);
        pl.y = (uint32_t)__bfloat16_as_ushort(l2) | ((uint32_t)__bfloat16_as_ushort(l3) << 16);
        *(uint2*)(Ohi + off) = ph;
        *(uint2*)(Olo + off) = pl;
    }
}

// ---------------------------------------------------------------------------
// Launch
// ---------------------------------------------------------------------------
extern "C" void kernel_launch(void* const* d_in, const int* in_sizes, int n_in,
                              void* d_out, int out_size)
{
    (void)in_sizes; (void)n_in; (void)out_size;
    const float* x  = (const float*)d_in[0];
    const float* Wq = (const float*)d_in[1];
    const float* bq = (const float*)d_in[2];
    const float* Wk = (const float*)d_in[3];
    const float* bk = (const float*)d_in[4];
    const float* Wv = (const float*)d_in[5];
    const float* bv = (const float*)d_in[6];
    const float* Wo = (const float*)d_in[7];
    const float* bo = (const float*)d_in[8];
    float* out = (float*)d_out;

    void *pq, *pk, *pv, *pxh, *pxl, *pah, *pal, *pwh, *pwl;
    cudaGetSymbolAddress(&pq,  g_Q);
    cudaGetSymbolAddress(&pk,  g_K);
    cudaGetSymbolAddress(&pv,  g_V);
    cudaGetSymbolAddress(&pxh, g_xhi);
    cudaGetSymbolAddress(&pxl, g_xlo);
    cudaGetSymbolAddress(&pah, g_ahi);
    cudaGetSymbolAddress(&pal, g_alo);
    cudaGetSymbolAddress(&pwh, g_whi);
    cudaGetSymbolAddress(&pwl, g_wlo);
    float* Qp = (float*)pq;
    float* Kp = (float*)pk;
    float* Vp = (float*)pv;
    __nv_bfloat16* xhi = (__nv_bfloat16*)pxh;
    __nv_bfloat16* xlo = (__nv_bfloat16*)pxl;
    __nv_bfloat16* ahi = (__nv_bfloat16*)pah;
    __nv_bfloat16* alo = (__nv_bfloat16*)pal;
    __nv_bfloat16* whi = (__nv_bfloat16*)pwh;
    __nv_bfloat16* wlo = (__nv_bfloat16*)pwl;

    const size_t WSZ = (size_t)EMBED * EMBED;

    // 1) fp32 -> bf16 hi/lo conversions
    conv_x<<<(NTOK * EMBED) / (256 * 4), 256>>>(x, xhi, xlo);
    conv_wT<<<dim3(32, 32, 4), dim3(32, 8)>>>(Wq, Wk, Wv, Wo, whi, wlo);

    // 2) fused QKV projection on tensor cores (z selects W/bias/dest)
    dim3 g1(EMBED / 128, NTOK / 128, 3);
    gemm_mma<<<g1, 256>>>(xhi, xlo,
                          whi, whi + WSZ, whi + 2 * WSZ,
                          wlo, wlo + WSZ, wlo + 2 * WSZ,
                          bq, bk, bv, Qp, Kp, Vp);

    // 3) causal flash attention (fp32), epilogue emits bf16 hi/lo
    dim3 g2(TSEQ / 64, NH, 2);
    flash_attn<<<g2, 256>>>(Qp, Kp, Vp, ahi, alo);

    // 4) output projection on tensor cores
    dim3 g3(EMBED / 128, NTOK / 128, 1);
    gemm_mma<<<g3, 256>>>(ahi, alo,
                          whi + 3 * WSZ, whi + 3 * WSZ, whi + 3 * WSZ,
                          wlo + 3 * WSZ, wlo + 3 * WSZ, wlo + 3 * WSZ,
                          bo, bo, bo, out, out, out);
}